// round 16
// baseline (speedup 1.0000x reference)
#include <cuda_runtime.h>
#include <cuda_fp16.h>
#include <cstdint>

#define BB   4
#define CC   512
#define NSEQ 4096
#define DQK  64
#define LOG2E 1.4426950408889634f

// ---------------- scratch (static device globals: allocation-free) ----------
__device__ __half g_qh[BB * NSEQ * DQK];            // [b][i][d] hi
__device__ __half g_ql[BB * NSEQ * DQK];            // [b][i][d] lo
__device__ __half g_kh[BB * NSEQ * DQK];            // [b][j][d] hi
__device__ __half g_kl[BB * NSEQ * DQK];            // [b][j][d] lo
__device__ __half g_v [(size_t)BB * CC * NSEQ];     // [b][c][j] single fp16

__device__ __forceinline__ float ex2f(float x) {
    float r; asm("ex2.approx.f32 %0, %1;" : "=f"(r) : "f"(x)); return r;
}
__device__ __forceinline__ uint32_t smem_u32(const void* p) {
    uint32_t a;
    asm("{ .reg .u64 t; cvta.to.shared.u64 t, %1; cvt.u32.u64 %0, t; }" : "=r"(a) : "l"(p));
    return a;
}
__device__ __forceinline__ uint32_t pack_h2(float a, float b) {
    __half2 h = __floats2half2_rn(a, b);
    return *(uint32_t*)&h;
}
__device__ __forceinline__ uint32_t h2mul(uint32_t a, uint32_t b) {
    uint32_t r;
    asm("mul.rn.f16x2 %0, %1, %2;" : "=r"(r) : "r"(a), "r"(b));
    return r;
}
__device__ __forceinline__ void mma_f16(float* c, const uint32_t* a, uint32_t b0, uint32_t b1) {
    asm volatile("mma.sync.aligned.m16n8k16.row.col.f32.f16.f16.f32 "
        "{%0,%1,%2,%3}, {%4,%5,%6,%7}, {%8,%9}, {%0,%1,%2,%3};"
        : "+f"(c[0]), "+f"(c[1]), "+f"(c[2]), "+f"(c[3])
        : "r"(a[0]), "r"(a[1]), "r"(a[2]), "r"(a[3]), "r"(b0), "r"(b1));
}
__device__ __forceinline__ void ldsm4(uint32_t* r, uint32_t a) {
    asm volatile("ldmatrix.sync.aligned.m8n8.x4.shared.b16 {%0,%1,%2,%3}, [%4];"
        : "=r"(r[0]), "=r"(r[1]), "=r"(r[2]), "=r"(r[3]) : "r"(a));
}
__device__ __forceinline__ void cp16(uint32_t dst, const void* src) {
    asm volatile("cp.async.cg.shared.global [%0], [%1], 16;" :: "r"(dst), "l"(src));
}
#define CP_COMMIT() asm volatile("cp.async.commit_group;" ::: "memory")
#define CP_WAIT0()  asm volatile("cp.async.wait_group 0;" ::: "memory")
__device__ __forceinline__ void sts32(uint32_t a, uint32_t v) {
    asm volatile("st.shared.b32 [%0], %1;" :: "r"(a), "r"(v) : "memory");
}
__device__ __forceinline__ float lds32f(uint32_t a) {
    float v; asm volatile("ld.shared.f32 %0, [%1];" : "=f"(v) : "r"(a)); return v;
}
__device__ __forceinline__ void sts32f(uint32_t a, float v) {
    asm volatile("st.shared.f32 [%0], %1;" :: "r"(a), "f"(v) : "memory");
}

// ---------------- pass 1: QKV projection (SIMT fp32, 128x128 tile) ----------
#define PW 140
#define PX 132

__global__ __launch_bounds__(256) void proj_kernel(
    const float* __restrict__ x,
    const float* __restrict__ wq, const float* __restrict__ bq,
    const float* __restrict__ wk, const float* __restrict__ bk,
    const float* __restrict__ wv, const float* __restrict__ bv)
{
    __shared__ float ws[16][PW];
    __shared__ float xs[16][PX];
    __shared__ __half hs[128][68];

    const int b  = blockIdx.z;
    const int o0 = blockIdx.y * 128;
    const int n0 = blockIdx.x * 128;
    const int t  = threadIdx.x;
    const int tx = t & 15;
    const int ty = t >> 4;

    const float* wptr[2];
    int wrow[2];
    const int wc4 = (t & 3) * 4;
#pragma unroll
    for (int r = 0; r < 2; r++) {
        int row = r * 64 + (t >> 2);
        wrow[r] = row;
        int o = o0 + row;
        const float* base;
        if (o < 64)        base = wq + (size_t)o * CC;
        else if (o < 128)  base = wk + (size_t)(o - 64) * CC;
        else               base = wv + (size_t)(o - 128) * CC;
        wptr[r] = base + wc4;
    }
    const int xn4 = (t & 31) * 4;
    const float* xptr[2];
    int xcr[2];
#pragma unroll
    for (int r = 0; r < 2; r++) {
        int c = r * 8 + (t >> 5);
        xcr[r] = c;
        xptr[r] = x + ((size_t)(b * CC) + c) * NSEQ + n0 + xn4;
    }

    float acc[8][8];
#pragma unroll
    for (int i = 0; i < 8; i++)
#pragma unroll
        for (int j = 0; j < 8; j++) acc[i][j] = 0.f;

    for (int c0 = 0; c0 < CC; c0 += 16) {
        float4 w4[2], x4[2];
#pragma unroll
        for (int r = 0; r < 2; r++) {
            w4[r] = *(const float4*)(wptr[r] + c0);
            x4[r] = *(const float4*)(xptr[r] + (size_t)c0 * NSEQ);
        }
        __syncthreads();
#pragma unroll
        for (int r = 0; r < 2; r++) {
            ws[wc4 + 0][wrow[r]] = w4[r].x;
            ws[wc4 + 1][wrow[r]] = w4[r].y;
            ws[wc4 + 2][wrow[r]] = w4[r].z;
            ws[wc4 + 3][wrow[r]] = w4[r].w;
            *(float4*)&xs[xcr[r]][xn4] = x4[r];
        }
        __syncthreads();
#pragma unroll
        for (int c = 0; c < 16; c++) {
            float4 a0 = *(const float4*)&ws[c][4 * ty];
            float4 a1 = *(const float4*)&ws[c][4 * ty + 64];
            float4 b0 = *(const float4*)&xs[c][4 * tx];
            float4 b1 = *(const float4*)&xs[c][4 * tx + 64];
            float av[8] = {a0.x, a0.y, a0.z, a0.w, a1.x, a1.y, a1.z, a1.w};
            float bv2[8] = {b0.x, b0.y, b0.z, b0.w, b1.x, b1.y, b1.z, b1.w};
#pragma unroll
            for (int i = 0; i < 8; i++)
#pragma unroll
                for (int j = 0; j < 8; j++)
                    acc[i][j] = fmaf(av[i], bv2[j], acc[i][j]);
        }
    }

    if (blockIdx.y == 0) {
        const int nl_r = t & 63;
        const int sel  = (t >> 6) & 1;
        const int kq   = t >> 7;
#pragma unroll
        for (int h = 0; h < 2; h++) {
#pragma unroll
            for (int pass = 0; pass < 2; pass++) {
                __syncthreads();
#pragma unroll
                for (int i = 0; i < 8; i++) {
                    int o = 4 * ty + (i >> 2) * 64 + (i & 3);
                    int d = o & 63;
                    float bias = (o < 64) ? bq[d] : bk[d];
#pragma unroll
                    for (int jj = 0; jj < 4; jj++) {
                        int j = h * 4 + jj;
                        int nl = 4 * tx + (j & 3);
                        float v = acc[i][j] + bias;
                        __half hh = __float2half_rn(v);
                        if (pass) hh = __float2half_rn(v - __half2float(hh));
                        hs[o][nl] = hh;
                    }
                }
                __syncthreads();
                __half* dst;
                if (pass == 0) dst = sel ? g_kh : g_qh;
                else           dst = sel ? g_kl : g_ql;
                int n = n0 + h * 64 + nl_r;
                __half buf[32];
#pragma unroll
                for (int d = 0; d < 32; d++)
                    buf[d] = hs[sel * 64 + kq * 32 + d][nl_r];
                uint4* dp = (uint4*)(dst + ((size_t)(b * NSEQ) + n) * DQK + kq * 32);
#pragma unroll
                for (int k = 0; k < 4; k++)
                    dp[k] = ((uint4*)buf)[k];
            }
        }
    } else {
#pragma unroll
        for (int i = 0; i < 8; i++) {
            int c = (blockIdx.y - 1) * 128 + 4 * ty + (i >> 2) * 64 + (i & 3);
            float bias = bv[c];
#pragma unroll
            for (int k = 0; k < 2; k++) {
                int n = n0 + 4 * tx + k * 64;
                uint2 w2;
                w2.x = pack_h2(acc[i][4 * k + 0] + bias, acc[i][4 * k + 1] + bias);
                w2.y = pack_h2(acc[i][4 * k + 2] + bias, acc[i][4 * k + 3] + bias);
                *(uint2*)&g_v[((size_t)(b * CC + c)) * NSEQ + n] = w2;
            }
        }
    }
}

// ---------------- pass 2: HMMA flash attention, zero-redundancy GEMM1 -------
// CTA = 64 i x 512 c, 8 warps = (ig 0..3) x (ch 0..1). 2 barriers/chunk:
// top barrier doubles as prev-chunk completion fence (prefetch issued after).
// Row sums: fp32 partials during exp + correction fold (no ones-MMA).
#define KROW   144
#define S_Q    0                     /* Q hi 9216 | lo 9216 */
#define S_P    18432                 /* P: 64 x 144 = 9216 */
#define S_MX   27648                 /* chunk max: 2 x 64 floats */
#define S_PS   28160                 /* partial row sums: 2 x 64 floats */
#define S_BUF  28672
#define SK_H   0
#define SK_L   9216
#define SV     18432
#define TILE_BYTES 92160             /* K 2x9216 + V 512x144 */
#define N_CHUNK (NSEQ / 64)
#define STG_ROW 68
#define OUT_SMEM_BYTES (S_BUF + 2 * TILE_BYTES)   /* 212992 */

__device__ __forceinline__ void issue_tiles(uint32_t tb, int b, int j0, int t)
{
#pragma unroll
    for (int r = 0; r < 4; r++) {           // K hi+lo: 1024 16B chunks
        int idx = t + r * 256;
        int arr = idx >> 9;
        int row = (idx >> 3) & 63;
        int col = idx & 7;
        const __half* src = (arr ? g_kl : g_kh) + ((size_t)b * NSEQ + j0 + row) * DQK + col * 8;
        cp16(tb + SK_H + arr * 9216 + row * KROW + col * 16, src);
    }
#pragma unroll
    for (int r = 0; r < 16; r++) {          // V: 4096 16B chunks (512 c rows)
        int idx = t + r * 256;
        int row = (idx >> 3) & 511;
        int col = idx & 7;
        const __half* src = g_v + ((size_t)(b * CC) + row) * NSEQ + j0 + col * 8;
        cp16(tb + SV + row * KROW + col * 16, src);
    }
}

__global__ __launch_bounds__(256, 1) void out_kernel(float* __restrict__ out)
{
    extern __shared__ char smem[];
    const uint32_t sb = smem_u32(smem);
    const int b  = blockIdx.z;
    const int i0 = blockIdx.x * 64;
    const int t  = threadIdx.x;
    const int w  = t >> 5;
    const int lane = t & 31;
    const int g  = lane >> 2;
    const int t4 = lane & 3;
    const int l8 = lane & 7;
    const int tt = lane >> 3;
    const int ig = w & 3;
    const int ch = w >> 2;

    // stage Q hi/lo [64 i][64 d] + tile 0
#pragma unroll
    for (int r = 0; r < 4; r++) {
        int idx = t + r * 256;
        int arr = idx >> 9;
        int row = (idx >> 3) & 63;
        int col = idx & 7;
        const __half* src = (arr ? g_ql : g_qh) + ((size_t)b * NSEQ + i0 + row) * DQK + col * 8;
        cp16(sb + S_Q + arr * 9216 + row * KROW + col * 16, src);
    }
    issue_tiles(sb + S_BUF, b, 0, t);
    CP_COMMIT();

    const uint32_t frow = (uint32_t)(ig * 16 + l8 + ((lane >> 3) & 1) * 8) * KROW
                        + (uint32_t)((lane >> 4) * 16);
    const uint32_t qlrow = sb + S_Q + frow;
    const uint32_t prow  = sb + S_P + frow;
    const uint32_t psts0 = sb + S_P + (uint32_t)(ig * 16 + g) * KROW + (uint32_t)(ch * 64 + 4 * t4);
    const uint32_t psts1 = psts0 + 8 * KROW;
    const uint32_t mrow0 = sb + S_MX + (uint32_t)(ig * 16 + g) * 4;
    const uint32_t srow0 = sb + S_PS + (uint32_t)(ig * 16 + g) * 4;

    float o[32][4];
#pragma unroll
    for (int ct = 0; ct < 32; ct++)
#pragma unroll
        for (int r = 0; r < 4; r++) o[ct][r] = 0.f;
    float la0 = 0.f, la1 = 0.f;
    float m0 = -1e30f, m1 = -1e30f;

    for (int it = 0; it < N_CHUNK; ++it) {
        CP_WAIT0();
        __syncthreads();    // prev chunk fully done everywhere + tile it visible
        if (it + 1 < N_CHUNK) {
            issue_tiles(sb + S_BUF + ((it + 1) & 1) * TILE_BYTES, b, (it + 1) * 64, t);
            CP_COMMIT();
        }

        const uint32_t tb = sb + S_BUF + (it & 1) * TILE_BYTES;

        // ---- GEMM1: S = Q K^T for 16i x 32j (split-3 fp16) ----
        float s[4][4];
#pragma unroll
        for (int q = 0; q < 4; q++)
#pragma unroll
            for (int r = 0; r < 4; r++) s[q][r] = 0.f;

#pragma unroll
        for (int kp = 0; kp < 2; kp++) {
            uint32_t qh0[4], qh1[4], ql0[4], ql1[4];
            uint32_t qcol = (uint32_t)(kp * 64);
            ldsm4(qh0, qlrow + qcol);
            ldsm4(qh1, qlrow + qcol + 32);
            ldsm4(ql0, qlrow + 9216 + qcol);
            ldsm4(ql1, qlrow + 9216 + qcol + 32);
#pragma unroll
            for (int q = 0; q < 4; q++) {
                int nt = ch * 4 + q;
                uint32_t krow = tb + (nt * 8 + l8) * KROW + tt * 16;
                uint32_t kh[4], kl[4];
                ldsm4(kh, krow + SK_H + kp * 64);
                ldsm4(kl, krow + SK_L + kp * 64);
                mma_f16(s[q], qh0, kh[0], kh[1]);
                mma_f16(s[q], qh1, kh[2], kh[3]);
                mma_f16(s[q], ql0, kh[0], kh[1]);
                mma_f16(s[q], ql1, kh[2], kh[3]);
                mma_f16(s[q], qh0, kl[0], kl[1]);
                mma_f16(s[q], qh1, kl[2], kl[3]);
            }
        }

        // ---- own-half row chunk-max (log2 units) ----
        float cm0 = -1e30f, cm1 = -1e30f;
#pragma unroll
        for (int q = 0; q < 4; q++) {
            cm0 = fmaxf(cm0, fmaxf(s[q][0], s[q][1]));
            cm1 = fmaxf(cm1, fmaxf(s[q][2], s[q][3]));
        }
        cm0 = fmaxf(cm0, __shfl_xor_sync(0xFFFFFFFFu, cm0, 1));
        cm0 = fmaxf(cm0, __shfl_xor_sync(0xFFFFFFFFu, cm0, 2));
        cm1 = fmaxf(cm1, __shfl_xor_sync(0xFFFFFFFFu, cm1, 1));
        cm1 = fmaxf(cm1, __shfl_xor_sync(0xFFFFFFFFu, cm1, 2));
        const float cmL0 = cm0 * LOG2E;
        const float cmL1 = cm1 * LOG2E;

        // ---- exp in OWN-chunk frame + fp32 partial sums + STS P ----
        float ps0 = 0.f, ps1 = 0.f;
#pragma unroll
        for (int kt = 0; kt < 2; kt++) {
            float pg0 = ex2f(fmaf(s[2 * kt][0],     LOG2E, -cmL0));
            float pg1 = ex2f(fmaf(s[2 * kt][1],     LOG2E, -cmL0));
            float pg2 = ex2f(fmaf(s[2 * kt + 1][0], LOG2E, -cmL0));
            float pg3 = ex2f(fmaf(s[2 * kt + 1][1], LOG2E, -cmL0));
            float ph0 = ex2f(fmaf(s[2 * kt][2],     LOG2E, -cmL1));
            float ph1 = ex2f(fmaf(s[2 * kt][3],     LOG2E, -cmL1));
            float ph2 = ex2f(fmaf(s[2 * kt + 1][2], LOG2E, -cmL1));
            float ph3 = ex2f(fmaf(s[2 * kt + 1][3], LOG2E, -cmL1));
            ps0 += (pg0 + pg1) + (pg2 + pg3);
            ps1 += (ph0 + ph1) + (ph2 + ph3);
            sts32(psts0 + kt * 32,      pack_h2(pg0, pg1));
            sts32(psts0 + kt * 32 + 16, pack_h2(pg2, pg3));
            sts32(psts1 + kt * 32,      pack_h2(ph0, ph1));
            sts32(psts1 + kt * 32 + 16, pack_h2(ph2, ph3));
        }
        ps0 += __shfl_xor_sync(0xFFFFFFFFu, ps0, 1);
        ps0 += __shfl_xor_sync(0xFFFFFFFFu, ps0, 2);
        ps1 += __shfl_xor_sync(0xFFFFFFFFu, ps1, 1);
        ps1 += __shfl_xor_sync(0xFFFFFFFFu, ps1, 2);
        if (t4 == 0) {
            sts32f(mrow0 + (uint32_t)(ch * 256), cmL0);
            sts32f(mrow0 + (uint32_t)(ch * 256) + 32, cmL1);
            sts32f(srow0 + (uint32_t)(ch * 256), ps0);
            sts32f(srow0 + (uint32_t)(ch * 256) + 32, ps1);
        }
        __syncthreads();

        // ---- global frame update + correction factors + la fold ----
        const float h0r0 = lds32f(mrow0);
        const float h1r0 = lds32f(mrow0 + 256);
        const float h0r1 = lds32f(mrow0 + 32);
        const float h1r1 = lds32f(mrow0 + 32 + 256);
        float m0n = fmaxf(m0, fmaxf(h0r0, h1r0));
        float m1n = fmaxf(m1, fmaxf(h0r1, h1r1));
        float f0 = ex2f(m0 - m0n);
        float f1 = ex2f(m1 - m1n);
        m0 = m0n; m1 = m1n;
        const float e00 = ex2f(h0r0 - m0n);
        const float e10 = ex2f(h1r0 - m0n);
        const float e01 = ex2f(h0r1 - m1n);
        const float e11 = ex2f(h1r1 - m1n);
        la0 = fmaf(lds32f(srow0), e00,
              fmaf(lds32f(srow0 + 256), e10, la0 * f0));
        la1 = fmaf(lds32f(srow0 + 32), e01,
              fmaf(lds32f(srow0 + 32 + 256), e11, la1 * f1));
        if (__any_sync(0xFFFFFFFFu, fminf(f0, f1) < 0.9999995f)) {
#pragma unroll
            for (int ct = 0; ct < 32; ct++) {
                o[ct][0] *= f0; o[ct][1] *= f0;
                o[ct][2] *= f1; o[ct][3] *= f1;
            }
        }
        const uint32_t c0r0 = pack_h2(e00, e00);
        const uint32_t c1r0 = pack_h2(e10, e10);
        const uint32_t c0r1 = pack_h2(e01, e01);
        const uint32_t c1r1 = pack_h2(e11, e11);

        // ---- load full-row P fragments, correct to global frame ----
        uint32_t pa[4][4];
#pragma unroll
        for (int kt = 0; kt < 4; kt++)
            ldsm4(pa[kt], prow + kt * 32);
#pragma unroll
        for (int kt = 0; kt < 4; kt++) {
            const uint32_t cr0 = (kt >> 1) ? c1r0 : c0r0;
            const uint32_t cr1 = (kt >> 1) ? c1r1 : c0r1;
            pa[kt][0] = h2mul(pa[kt][0], cr0);
            pa[kt][1] = h2mul(pa[kt][1], cr1);
            pa[kt][2] = h2mul(pa[kt][2], cr0);
            pa[kt][3] = h2mul(pa[kt][3], cr1);
        }

        // ---- GEMM2: o += P V^T, warp tile 16i x 256c ----
#pragma unroll
        for (int ct = 0; ct < 32; ct++) {
            uint32_t vrow = tb + SV + (ch * 256 + ct * 8 + l8) * KROW + tt * 16;
#pragma unroll
            for (int jh = 0; jh < 2; jh++) {
                uint32_t vv[4];
                ldsm4(vv, vrow + jh * 64);
                mma_f16(o[ct], pa[2 * jh],     vv[0], vv[1]);
                mma_f16(o[ct], pa[2 * jh + 1], vv[2], vv[3]);
            }
        }
        // no end barrier: next iteration's top barrier is the fence
    }

    const float li0 = 1.0f / la0;
    const float li1 = 1.0f / la1;

    __syncthreads();   // all warps done reading P/V before stg overlay
    // epilogue: scale, transpose through SMEM staging (512c x 64i), store
    float* stg = (float*)smem;
    const int il = ig * 16 + g;
#pragma unroll
    for (int ct = 0; ct < 32; ct++) {
        int c = ch * 256 + ct * 8 + 2 * t4;
        stg[(size_t)c * STG_ROW + il]           = o[ct][0] * li0;
        stg[(size_t)(c + 1) * STG_ROW + il]     = o[ct][1] * li0;
        stg[(size_t)c * STG_ROW + il + 8]       = o[ct][2] * li1;
        stg[(size_t)(c + 1) * STG_ROW + il + 8] = o[ct][3] * li1;
    }
    __syncthreads();
#pragma unroll
    for (int r = 0; r < 32; r++) {
        int fid = t + r * 256;               // 8192 float4 = 512c x 16
        int c = fid >> 4, x = fid & 15;
        float4 v = *(const float4*)&stg[(size_t)c * STG_ROW + x * 4];
        *(float4*)(out + ((size_t)(b * CC + c)) * NSEQ + i0 + x * 4) = v;
    }
}

// ---------------- launch ----------------------------------------------------
extern "C" void kernel_launch(void* const* d_in, const int* in_sizes, int n_in,
                              void* d_out, int out_size)
{
    const float* x  = (const float*)d_in[0];
    const float* wq = (const float*)d_in[1];
    const float* bq = (const float*)d_in[2];
    const float* wk = (const float*)d_in[3];
    const float* bk = (const float*)d_in[4];
    const float* wv = (const float*)d_in[5];
    const float* bv = (const float*)d_in[6];
    float* out = (float*)d_out;

    proj_kernel<<<dim3(NSEQ / 128, 5, BB), 256>>>(x, wq, bq, wk, bk, wv, bv);
    cudaFuncSetAttribute(out_kernel, cudaFuncAttributeMaxDynamicSharedMemorySize, OUT_SMEM_BYTES);
    out_kernel<<<dim3(NSEQ / 64, 1, BB), 256, OUT_SMEM_BYTES>>>(out);
}